// round 11
// baseline (speedup 1.0000x reference)
#include <cuda_runtime.h>
#include <stdint.h>
#include <math.h>

#define NA 180
#define NH 256
#define NW 256
#define ND 256
#define NB 16
#define NT 5
#define NP (NH*NW)
#define NRC (NA*ND)
#define CAP 256
#define CAPP 192
#define MPI 3.14159265358979323846

#define TPC  ((float)(2.0 * MPI))
#define RCPC ((float)(1.0 / (double)((float)(2.0 * MPI))))

// ---------------- device globals (no allocation allowed) ----------------
__device__ float g_C[NA];
__device__ float g_S[NA];
__device__ int   g_row[NA];
__device__ ushort4 g_meta[NA * NH];                         // xlo, xhi, leftbin, rightbin
__device__ __align__(64) float g_img[NP * NB];              // 4 MB, [pixel][batch]
__device__ __align__(64) float g_P[NH * 257 * NB];          // row prefix sums [y][x][b]
__device__ __align__(64) float g_R[NRC * NB];               // residual [a*256+bin][b]
__device__ __align__(64) float g_SN[NRC * NB];              // sino rows transposed
__device__ int g_cnt[NRC];                                  // FP run counts
__device__ unsigned g_runs[NRC * CAP];                      // FP runs y|x0<<8|x1<<17
__device__ int g_pcnt[NP];                                  // per-pixel entry counts
__device__ __align__(8) uint16_t g_plist[NP * CAPP];        // per-pixel entries a<<8|bin
__device__ unsigned g_maxbits;

// launch #1: angles + zero all counters
__global__ void k_pre() {
    int gid = blockIdx.x * 256 + threadIdx.x;
    int stride = gridDim.x * 256;
    if (gid < NA) {
        double ad = (double)gid * (MPI / 179.0);
        float ang = (float)ad;
        if (gid == NA - 1) ang = (float)MPI;            // linspace endpoint
        g_C[gid] = (float)cos((double)ang);
        g_S[gid] = (float)sin((double)ang);
        float r = __fmul_rn(__fdiv_rn(ang, (float)MPI), 179.0f);
        g_row[gid] = (int)r;
    }
    for (int j = gid; j < NP; j += stride) g_pcnt[j] = 0;
    for (int j = gid; j < NRC; j += stride) g_cnt[j] = 0;
    if (gid == 0) g_maxbits = 0u;
}

// launch #2: zero image + prefix array, sino transpose + iteration-0 R seed
__global__ void k_pre2(const float* __restrict__ sino) {
    int i = blockIdx.x * blockDim.x + threadIdx.x;
    int stride = gridDim.x * blockDim.x;
    for (int j = i; j < NP * NB; j += stride) g_img[j] = 0.0f;
    for (int j = i; j < NH * 257 * NB; j += stride) g_P[j] = 0.0f;
    for (int j = i; j < NRC * NB; j += stride) {
        int b = j & 15;
        int ad = j >> 4;                  // a*256+d
        int a = ad >> 8, d = ad & 255;
        float sv = sino[(size_t)b * (NA * ND) + g_row[a] * ND + d];
        g_SN[j] = sv;
        g_R[j] = sv;                       // image==0 -> residual = sino
    }
}

// launch #3: bins + meta + FP runs + per-pixel BP lists, x-parallel
__global__ __launch_bounds__(256) void k_binsfill() {
    __shared__ int sbin[256];
    __shared__ int s_xlo, s_lastchg;
    int a = blockIdx.x;
    int x = threadIdx.x;
    float c = g_C[a], s = g_S[a];
    float xc = (float)x - 128.0f;
    int cb = a * ND;
    int y0 = blockIdx.y * 32;
    for (int y = y0; y < y0 + 32; y++) {
        float tY = __fmul_rn((float)y - 128.0f, s);
        float rot = __fadd_rn(__fmul_rn(xc, c), tY);
        float q = __fmul_rn(rot, RCPC);                  // Markstein /2pi (RN exact)
        float r = __fmaf_rn(-TPC, q, rot);
        q = __fmaf_rn(r, RCPC, q);
        float v = __fmul_rn(q, 256.0f);
        v = truncf(v);
        v = fminf(fmaxf(v, 0.0f), 255.0f);
        int bin = (int)v;
        sbin[x] = bin;
        if (x == 0) { s_xlo = 256; s_lastchg = 0; }
        __syncthreads();
        bool chg = (x > 0 && bin != sbin[x - 1]);
        if (chg) {
            atomicMin(&s_xlo, x);
            atomicMax(&s_lastchg, x);
        }
        if ((x == 0 || chg) && bin > 0 && bin < 255) {
            int e = x + 1;
            while (e < 256 && sbin[e] == bin) e++;       // interior runs <= ~4 px
            int pos = atomicAdd(&g_cnt[cb + bin], 1);
            g_runs[(size_t)(cb + bin) * CAP + pos] =
                (unsigned)y | ((unsigned)x << 8) | ((unsigned)e << 17);
        }
        __syncthreads();
        int xlo = s_xlo, xhi = s_lastchg;
        if (xhi < xlo) xhi = xlo;                        // constant row
        if (x >= xlo && x < xhi) {                       // per-pixel BP entry
            int p = (y << 8) + x;
            int pos = atomicAdd(&g_pcnt[p], 1);
            g_plist[(size_t)p * CAPP + pos] = (uint16_t)((a << 8) | bin);
        }
        if (x == 0)
            g_meta[a * NH + y] = make_ushort4((unsigned short)xlo, (unsigned short)xhi,
                                              (unsigned short)sbin[0],
                                              (unsigned short)sbin[255]);
        __syncthreads();
    }
}

// monolithic BP + update + fused prefix (+max); block = (row y, batch half h)
// grid 512 = 256 rows x 2 halves; each block owns channels [8h, 8h+8)
__global__ __launch_bounds__(512, 2) void k_bp(int last) {
    __shared__ float Dsh[257 * 9];
    __shared__ float Acc[256 * 9];
    __shared__ float Lw[16 * 9];
    __shared__ float blockmax[16];
    __shared__ int scnt[256];
    __shared__ ushort4 smeta[NA];
    int blk = blockIdx.x;
    int y = blk >> 1, bbase = (blk & 1) << 3;
    int t = threadIdx.x;
    int w = t >> 5, lane = t & 31;
    for (int i = t; i < 257 * 9; i += 512) Dsh[i] = 0.0f;
    if (t < 16 * 9) Lw[t] = 0.0f;
    if (t < 256) scnt[t] = g_pcnt[(y << 8) + t];         // preload counts
    else if (t - 256 < NA) smeta[t - 256] = g_meta[(t - 256) * NH + y];
    __syncthreads();
    // Phase A: terminal-run step contributions, item-parallel over (a, 8ch)
    for (int it = t; it < NA * 8; it += 512) {
        int a = it >> 3, c = it & 7, b = bbase + c;
        ushort4 m = smeta[a];
        int xlo = m.x, xhi = m.y, lb = m.z, rb = m.w;
        if (xlo > 0) {
            float v = g_R[((size_t)a * ND + lb) * NB + b];
            atomicAdd(&Lw[w * 9 + c], v);                // x=0 partials (hot)
            atomicAdd(&Dsh[xlo * 9 + c], -v);
        }
        if (xhi < 256) {
            float v = g_R[((size_t)a * ND + rb) * NB + b];
            atomicAdd(&Dsh[xhi * 9 + c], v);
        }
    }
    // Phase B: interior gather; warp = 4 px x 8 ch, MLP=8
    {
        int c = lane & 7, b = bbase + c;
        int sub = lane >> 3;                              // 0..3
        for (int p = 0; p < 4; p++) {
            int px = p * 64 + (w << 2) + sub;
            int pix = (y << 8) + px;
            int n = scnt[px];
            const uint16_t* lst = g_plist + (size_t)pix * CAPP;
            float a0 = 0.0f, a1 = 0.0f, a2 = 0.0f, a3 = 0.0f;
            float a4 = 0.0f, a5 = 0.0f, a6 = 0.0f, a7 = 0.0f;
            int i = 0;
            for (; i + 7 < n; i += 8) {
                ushort4 e0 = *(const ushort4*)(lst + i);
                ushort4 e1 = *(const ushort4*)(lst + i + 4);
                a0 += g_R[(size_t)e0.x * NB + b];
                a1 += g_R[(size_t)e0.y * NB + b];
                a2 += g_R[(size_t)e0.z * NB + b];
                a3 += g_R[(size_t)e0.w * NB + b];
                a4 += g_R[(size_t)e1.x * NB + b];
                a5 += g_R[(size_t)e1.y * NB + b];
                a6 += g_R[(size_t)e1.z * NB + b];
                a7 += g_R[(size_t)e1.w * NB + b];
            }
            if (i + 3 < n) {
                ushort4 e0 = *(const ushort4*)(lst + i);
                a0 += g_R[(size_t)e0.x * NB + b];
                a1 += g_R[(size_t)e0.y * NB + b];
                a2 += g_R[(size_t)e0.z * NB + b];
                a3 += g_R[(size_t)e0.w * NB + b];
                i += 4;
            }
            for (; i < n; i++) a0 += g_R[(size_t)lst[i] * NB + b];
            Acc[px * 9 + c] = ((a0 + a1) + (a2 + a3)) + ((a4 + a5) + (a6 + a7));
        }
    }
    __syncthreads();
    // combine x=0 partials into Dsh[0]
    if (t < 8) {
        float s = 0.0f;
        #pragma unroll
        for (int k = 0; k < 16; k++) s += Lw[k * 9 + t];
        Dsh[t] += s;
    }
    __syncthreads();
    // Phase C: inclusive scan along x; warp w (<8) owns channel w; lane = 8 elems
    if (w < 8) {
        float s[8];
        int base = lane * 8;
        #pragma unroll
        for (int k = 0; k < 8; k++) s[k] = Dsh[(base + k) * 9 + w];
        #pragma unroll
        for (int k = 1; k < 8; k++) s[k] += s[k - 1];
        float tot = s[7], inc = tot;
        #pragma unroll
        for (int off = 1; off < 32; off <<= 1) {
            float nn = __shfl_up_sync(0xffffffffu, inc, off);
            if (lane >= off) inc += nn;
        }
        float excl = inc - tot;
        #pragma unroll
        for (int k = 0; k < 8; k++) Dsh[(base + k) * 9 + w] = s[k] + excl;
    }
    __syncthreads();
    // Phase D: elementwise update over the 2048 owned elements
    float* irow = g_img + (size_t)y * NW * NB;
    float mx = -INFINITY;
    #pragma unroll
    for (int k = 0; k < 4; k++) {
        int i = t + k * 512;
        int x = i >> 3, c = i & 7;
        float corr = Acc[x * 9 + c] + Dsh[x * 9 + c];
        float nv = irow[x * NB + bbase + c] + __fdiv_rn(corr, 180.0f);
        irow[x * NB + bbase + c] = nv;
        Dsh[x * 9 + c] = nv;                  // stage for prefix (own slot)
        mx = fmaxf(mx, nv);
    }
    if (last) {
        #pragma unroll
        for (int off = 16; off; off >>= 1)
            mx = fmaxf(mx, __shfl_xor_sync(0xffffffffu, mx, off));
        if (lane == 0) blockmax[w] = mx;
    }
    __syncthreads();
    // Phase E: inclusive prefix of new row -> g_P; same fast scan
    if (w < 8) {
        float s[8];
        int base = lane * 8;
        #pragma unroll
        for (int k = 0; k < 8; k++) s[k] = Dsh[(base + k) * 9 + w];
        #pragma unroll
        for (int k = 1; k < 8; k++) s[k] += s[k - 1];
        float tot = s[7], inc = tot;
        #pragma unroll
        for (int off = 1; off < 32; off <<= 1) {
            float nn = __shfl_up_sync(0xffffffffu, inc, off);
            if (lane >= off) inc += nn;
        }
        float excl = inc - tot;
        #pragma unroll
        for (int k = 0; k < 8; k++) Dsh[(base + k) * 9 + w] = s[k] + excl;
    }
    __syncthreads();
    #pragma unroll
    for (int k = 0; k < 4; k++) {
        int i = t + k * 512;
        int x = i >> 3, c = i & 7;
        g_P[((size_t)y * 257 + x + 1) * NB + bbase + c] = Dsh[x * 9 + c];
    }
    if (last && t == 0) {
        float m = blockmax[0];
        #pragma unroll
        for (int k = 1; k < 16; k++) m = fmaxf(m, blockmax[k]);
        unsigned u = __float_as_uint(m);
        u = (u & 0x80000000u) ? ~u : (u | 0x80000000u);
        atomicMax(&g_maxbits, u);
    }
}

// fused FP: blocks [0, 5760) interior runs; blocks [5760, 6120) terminal bins
__global__ __launch_bounds__(256) void k_fpx() {
    __shared__ ushort4 sm2[256];
    __shared__ float red[16 * 17];
    int bx = blockIdx.x;
    int t = threadIdx.x;
    if (bx < NRC / 8) {
        // interior FP: warp per (a,d), zero atomics, MLP 8
        int wi = bx * 8 + (t >> 5);
        int d = wi & 255;
        if (d == 0 || d == 255) return;                  // terminal handled below
        int lane = t & 31, half = lane >> 4, b = lane & 15;
        int n = g_cnt[wi];
        const unsigned* runs = g_runs + (size_t)wi * CAP;
        float acc = 0.0f, acc2 = 0.0f, acc3 = 0.0f, acc4 = 0.0f;
        int r = half;
        for (; r + 6 < n; r += 8) {
            unsigned r1 = runs[r], r2 = runs[r + 2], r3 = runs[r + 4], r4 = runs[r + 6];
            const float* P1 = g_P + (size_t)(r1 & 255) * 257 * NB;
            const float* P2 = g_P + (size_t)(r2 & 255) * 257 * NB;
            const float* P3 = g_P + (size_t)(r3 & 255) * 257 * NB;
            const float* P4 = g_P + (size_t)(r4 & 255) * 257 * NB;
            acc  += P1[((r1 >> 17) & 511) * NB + b] - P1[((r1 >> 8) & 511) * NB + b];
            acc2 += P2[((r2 >> 17) & 511) * NB + b] - P2[((r2 >> 8) & 511) * NB + b];
            acc3 += P3[((r3 >> 17) & 511) * NB + b] - P3[((r3 >> 8) & 511) * NB + b];
            acc4 += P4[((r4 >> 17) & 511) * NB + b] - P4[((r4 >> 8) & 511) * NB + b];
        }
        for (; r < n; r += 2) {
            unsigned rec = runs[r];
            const float* Pr = g_P + (size_t)(rec & 255) * 257 * NB;
            acc += Pr[((rec >> 17) & 511) * NB + b] - Pr[((rec >> 8) & 511) * NB + b];
        }
        acc = (acc + acc2) + (acc3 + acc4);
        acc += __shfl_xor_sync(0xffffffffu, acc, 16);
        if (half == 0)
            g_R[(size_t)wi * NB + b] = g_SN[(size_t)wi * NB + b] - acc;
        return;
    }
    // terminal bins d in {0,255}: block per (a,side)
    int bx2 = bx - NRC / 8;
    int a = bx2 >> 1;
    int d = (bx2 & 1) ? 255 : 0;
    sm2[t] = g_meta[a * NH + t];
    __syncthreads();
    int b = t & 15, yg = t >> 4;
    float acc = 0.0f;
    #pragma unroll 4
    for (int i = 0; i < 16; i++) {
        int y = yg * 16 + i;
        ushort4 m = sm2[y];
        const float* Pr = g_P + (size_t)y * 257 * NB;
        if ((int)m.z == d)        acc += Pr[(int)m.x * NB + b];
        else if ((int)m.w == d)   acc += Pr[256 * NB + b] - Pr[(int)m.y * NB + b];
    }
    red[yg * 17 + b] = acc;
    __syncthreads();
    if (t < 16) {
        float s = 0.0f;
        #pragma unroll
        for (int g = 0; g < 16; g++) s += red[g * 17 + t];
        int wi = a * ND + d;
        g_R[(size_t)wi * NB + t] = g_SN[(size_t)wi * NB + t] - s;
    }
}

// output: clip(image, 0, gmax), coalesced transpose [p][b] -> [b][p]
__global__ __launch_bounds__(256) void k_out(float* __restrict__ out) {
    __shared__ float sh[256 * 17];
    int t = threadIdx.x;
    int p0 = blockIdx.x * 256;
    const float* src = g_img + (size_t)p0 * NB;
    for (int i = t; i < 256 * NB; i += 256) {
        int p = i >> 4, b = i & 15;
        sh[p * 17 + b] = src[i];
    }
    __syncthreads();
    unsigned u = g_maxbits;
    float gm = (u & 0x80000000u) ? __uint_as_float(u ^ 0x80000000u)
                                 : __uint_as_float(~u);
    #pragma unroll
    for (int b = 0; b < NB; b++) {
        float v = sh[t * 17 + b];
        out[(size_t)b * NP + p0 + t] = fminf(fmaxf(v, 0.0f), gm);
    }
}

extern "C" void kernel_launch(void* const* d_in, const int* in_sizes, int n_in,
                              void* d_out, int out_size) {
    const float* sino = (const float*)d_in[0];
    float* out = (float*)d_out;

    k_pre<<<64, 256>>>();
    k_pre2<<<512, 256>>>(sino);
    k_binsfill<<<dim3(NA, 8), 256>>>();
    k_bp<<<NH * 2, 512>>>(0);            // launch #4 -> ncu target (A/B vs 33.5us)
    for (int it = 1; it < NT; it++) {
        k_fpx<<<NRC / 8 + NA * 2, 256>>>();
        k_bp<<<NH * 2, 512>>>(it == NT - 1 ? 1 : 0);
    }
    k_out<<<256, 256>>>(out);
}

// round 13
// speedup vs baseline: 1.0409x; 1.0409x over previous
#include <cuda_runtime.h>
#include <stdint.h>
#include <math.h>

#define NA 180
#define NH 256
#define NW 256
#define ND 256
#define NB 16
#define NT 5
#define NP (NH*NW)
#define NRC (NA*ND)
#define CAP 256
#define CAPP 192
#define STAGE_CAP 8192
#define MPI 3.14159265358979323846

#define TPC  ((float)(2.0 * MPI))
#define RCPC ((float)(1.0 / (double)((float)(2.0 * MPI))))

// k_bp dynamic smem layout (4-byte word offsets)
#define OFF_DSH   0                      // float[257*17] = 4369
#define OFF_ACC   4370                   // float[256*17] = 4352
#define OFF_LW    8722                   // float[16*17]  = 272
#define OFF_BMAX  8994                   // float[16]
#define OFF_SCNT  9010                   // int[256]
#define OFF_SOFF  9266                   // int[256]
#define OFF_WSUM  9522                   // int[8]
#define OFF_SMETA 9530                   // ushort4[180] = 360 words (8B aligned)
#define OFF_STAGE 9890                   // uint16[8192] = 4096 words
#define SMEM_WORDS 13986
#define SMEM_BYTES (SMEM_WORDS * 4)

// ---------------- device globals (no allocation allowed) ----------------
__device__ float g_C[NA];
__device__ float g_S[NA];
__device__ ushort4 g_meta[NA * NH];                         // xlo, xhi, leftbin, rightbin
__device__ __align__(64) float g_img[NP * NB];              // 4 MB, [pixel][batch]
__device__ __align__(64) float g_P[NH * 257 * NB];          // row prefix sums [y][x][b]
__device__ __align__(64) float g_R[NRC * NB];               // residual [a*256+bin][b]
__device__ __align__(64) float g_SN[NRC * NB];              // sino rows transposed
__device__ int g_cnt[NRC];                                  // FP run counts
__device__ unsigned g_runs[NRC * CAP];                      // FP runs y|x0<<8|x1<<17
__device__ int g_pcnt[NP];                                  // per-pixel entry counts
__device__ __align__(8) uint16_t g_plist[NP * CAPP];        // per-pixel entries a<<8|bin
__device__ unsigned g_maxbits;

// launch #1: angles + all zero-init + sino transpose + iteration-0 R seed
__global__ void k_pre(const float* __restrict__ sino) {
    int i = blockIdx.x * blockDim.x + threadIdx.x;
    int stride = gridDim.x * blockDim.x;
    if (i < NA) {
        double ad = (double)i * (MPI / 179.0);
        float ang = (float)ad;
        if (i == NA - 1) ang = (float)MPI;              // linspace endpoint
        g_C[i] = (float)cos((double)ang);
        g_S[i] = (float)sin((double)ang);
    }
    if (i == 0) g_maxbits = 0u;
    for (int j = i; j < NP; j += stride) g_pcnt[j] = 0;
    for (int j = i; j < NRC; j += stride) g_cnt[j] = 0;
    for (int j = i; j < NP * NB; j += stride) g_img[j] = 0.0f;
    for (int j = i; j < NH * 257 * NB; j += stride) g_P[j] = 0.0f;
    for (int j = i; j < NRC * NB; j += stride) {
        int b = j & 15;
        int ad = j >> 4;                  // a*256+d
        int a = ad >> 8, d = ad & 255;
        float ang = (float)((double)a * (MPI / 179.0));
        if (a == NA - 1) ang = (float)MPI;
        int row = (int)__fmul_rn(__fdiv_rn(ang, (float)MPI), 179.0f);
        float sv = sino[(size_t)b * (NA * ND) + row * ND + d];
        g_SN[j] = sv;
        g_R[j] = sv;                       // image==0 -> residual = sino
    }
}

// launch #2: bins + meta + FP runs + per-pixel BP lists, x-parallel
__global__ __launch_bounds__(256) void k_binsfill() {
    __shared__ int sbin[256];
    __shared__ int s_xlo, s_lastchg;
    int a = blockIdx.x;
    int x = threadIdx.x;
    float c = g_C[a], s = g_S[a];
    float xc = (float)x - 128.0f;
    int cb = a * ND;
    int y0 = blockIdx.y * 32;
    for (int y = y0; y < y0 + 32; y++) {
        float tY = __fmul_rn((float)y - 128.0f, s);
        float rot = __fadd_rn(__fmul_rn(xc, c), tY);
        float q = __fmul_rn(rot, RCPC);                  // Markstein /2pi (RN exact)
        float r = __fmaf_rn(-TPC, q, rot);
        q = __fmaf_rn(r, RCPC, q);
        float v = __fmul_rn(q, 256.0f);
        v = truncf(v);
        v = fminf(fmaxf(v, 0.0f), 255.0f);
        int bin = (int)v;
        sbin[x] = bin;
        if (x == 0) { s_xlo = 256; s_lastchg = 0; }
        __syncthreads();
        bool chg = (x > 0 && bin != sbin[x - 1]);
        if (chg) {
            atomicMin(&s_xlo, x);
            atomicMax(&s_lastchg, x);
        }
        if ((x == 0 || chg) && bin > 0 && bin < 255) {
            int e = x + 1;
            while (e < 256 && sbin[e] == bin) e++;       // interior runs <= ~4 px
            int pos = atomicAdd(&g_cnt[cb + bin], 1);
            g_runs[(size_t)(cb + bin) * CAP + pos] =
                (unsigned)y | ((unsigned)x << 8) | ((unsigned)e << 17);
        }
        __syncthreads();
        int xlo = s_xlo, xhi = s_lastchg;
        if (xhi < xlo) xhi = xlo;                        // constant row
        if (x >= xlo && x < xhi) {                       // per-pixel BP entry
            int p = (y << 8) + x;
            int pos = atomicAdd(&g_pcnt[p], 1);
            g_plist[(size_t)p * CAPP + pos] = (uint16_t)((a << 8) | bin);
        }
        if (x == 0)
            g_meta[a * NH + y] = make_ushort4((unsigned short)xlo, (unsigned short)xhi,
                                              (unsigned short)sbin[0],
                                              (unsigned short)sbin[255]);
        __syncthreads();
    }
}

// monolithic BP + update + fused prefix (+max); smem-staged index lists
__global__ __launch_bounds__(512) void k_bp(int last) {
    extern __shared__ __align__(16) unsigned smem_raw[];
    float*    Dsh      = (float*)(smem_raw + OFF_DSH);
    float*    Acc      = (float*)(smem_raw + OFF_ACC);
    float*    Lw       = (float*)(smem_raw + OFF_LW);
    float*    blockmax = (float*)(smem_raw + OFF_BMAX);
    int*      scnt     = (int*)(smem_raw + OFF_SCNT);
    int*      soff     = (int*)(smem_raw + OFF_SOFF);
    int*      wsum     = (int*)(smem_raw + OFF_WSUM);
    ushort4*  smeta    = (ushort4*)(smem_raw + OFF_SMETA);
    uint16_t* stage    = (uint16_t*)(smem_raw + OFF_STAGE);
    int y = blockIdx.x, t = threadIdx.x;
    int w = t >> 5, lane = t & 31;
    for (int i = t; i < 257 * 17; i += 512) Dsh[i] = 0.0f;
    if (t < 16 * 17) Lw[t] = 0.0f;
    if (t < 256) scnt[t] = g_pcnt[(y << 8) + t];         // preload counts
    else if (t - 256 < NA) smeta[t - 256] = g_meta[(t - 256) * NH + y];
    __syncthreads();
    // Phase 0a: even-padded exclusive scan of counts -> packed offsets
    int excl = 0;
    if (t < 256) {
        int v = (scnt[t] + 1) & ~1;                      // pad to even (u32 copy)
        int inc = v;
        #pragma unroll
        for (int off = 1; off < 32; off <<= 1) {
            int nn = __shfl_up_sync(0xffffffffu, inc, off);
            if (lane >= off) inc += nn;
        }
        if (lane == 31) wsum[w] = inc;
        excl = inc - v;
    }
    __syncthreads();
    if (t < 256) {
        int add = 0;
        #pragma unroll
        for (int k = 0; k < 8; k++) if (k < w) add += wsum[k];
        soff[t] = excl + add;
    }
    __syncthreads();
    // Phase 0b: bulk-copy per-pixel lists into packed smem (independent u32s)
    {
        int px = t >> 1, half = t & 1;
        int n = scnt[px];
        const uint32_t* src = (const uint32_t*)(g_plist + (size_t)((y << 8) + px) * CAPP);
        uint32_t* dst = (uint32_t*)stage + (soff[px] >> 1);
        int pairs = (n + 1) >> 1;
        for (int j = half; j < pairs; j += 2) dst[j] = src[j];
    }
    // Phase A: terminal-run step contributions, item-parallel over (a,b)
    for (int it = t; it < NA * NB; it += 512) {
        int a = it >> 4, b = it & 15;
        ushort4 m = smeta[a];
        int xlo = m.x, xhi = m.y, lb = m.z, rb = m.w;
        if (xlo > 0) {
            float v = g_R[((size_t)a * ND + lb) * NB + b];
            atomicAdd(&Lw[w * 17 + b], v);               // x=0 partials (hot)
            atomicAdd(&Dsh[xlo * 17 + b], -v);
        }
        if (xhi < 256) {
            float v = g_R[((size_t)a * ND + rb) * NB + b];
            atomicAdd(&Dsh[xhi * 17 + b], v);
        }
    }
    __syncthreads();                                     // stage complete
    // Phase B: interior gather; warp = 2 px x 16 batch; indices from smem, MLP=8
    {
        int b = lane & 15;
        int sub = lane >> 4;
        for (int p = 0; p < 8; p++) {
            int px = p * 32 + (w << 1) + sub;
            int n = scnt[px];
            const uint32_t* l32 = (const uint32_t*)stage + (soff[px] >> 1);
            float a0 = 0.0f, a1 = 0.0f, a2 = 0.0f, a3 = 0.0f;
            float a4 = 0.0f, a5 = 0.0f, a6 = 0.0f, a7 = 0.0f;
            int i = 0;
            for (; i + 7 < n; i += 8) {
                uint32_t w0 = l32[i >> 1], w1 = l32[(i >> 1) + 1];
                uint32_t w2 = l32[(i >> 1) + 2], w3 = l32[(i >> 1) + 3];
                a0 += g_R[(size_t)(w0 & 0xffffu) * NB + b];
                a1 += g_R[(size_t)(w0 >> 16) * NB + b];
                a2 += g_R[(size_t)(w1 & 0xffffu) * NB + b];
                a3 += g_R[(size_t)(w1 >> 16) * NB + b];
                a4 += g_R[(size_t)(w2 & 0xffffu) * NB + b];
                a5 += g_R[(size_t)(w2 >> 16) * NB + b];
                a6 += g_R[(size_t)(w3 & 0xffffu) * NB + b];
                a7 += g_R[(size_t)(w3 >> 16) * NB + b];
            }
            if (i + 3 < n) {
                uint32_t w0 = l32[i >> 1], w1 = l32[(i >> 1) + 1];
                a0 += g_R[(size_t)(w0 & 0xffffu) * NB + b];
                a1 += g_R[(size_t)(w0 >> 16) * NB + b];
                a2 += g_R[(size_t)(w1 & 0xffffu) * NB + b];
                a3 += g_R[(size_t)(w1 >> 16) * NB + b];
                i += 4;
            }
            const uint16_t* l16 = (const uint16_t*)l32;
            for (; i < n; i++) a0 += g_R[(size_t)l16[i] * NB + b];
            Acc[px * 17 + b] = ((a0 + a1) + (a2 + a3)) + ((a4 + a5) + (a6 + a7));
        }
    }
    __syncthreads();
    // combine x=0 partials into Dsh[0]
    if (t < 16) {
        float s = 0.0f;
        #pragma unroll
        for (int k = 0; k < 16; k++) s += Lw[k * 17 + t];
        Dsh[t] += s;
    }
    __syncthreads();
    // Phase C: inclusive scan along x; warp w owns channel w; lane = 8 elements
    {
        float s[8];
        int base = lane * 8;
        #pragma unroll
        for (int k = 0; k < 8; k++) s[k] = Dsh[(base + k) * 17 + w];
        #pragma unroll
        for (int k = 1; k < 8; k++) s[k] += s[k - 1];
        float tot = s[7], inc = tot;
        #pragma unroll
        for (int off = 1; off < 32; off <<= 1) {
            float nn = __shfl_up_sync(0xffffffffu, inc, off);
            if (lane >= off) inc += nn;
        }
        float excl2 = inc - tot;
        #pragma unroll
        for (int k = 0; k < 8; k++) Dsh[(base + k) * 17 + w] = s[k] + excl2;
    }
    __syncthreads();
    // Phase D: elementwise update over the 4096 row elements (each slot owned)
    float* irow = g_img + (size_t)y * NW * NB;
    float mx = -INFINITY;
    #pragma unroll
    for (int k = 0; k < 8; k++) {
        int i = t + k * 512;
        int x = i >> 4, b = i & 15;
        float corr = Acc[x * 17 + b] + Dsh[x * 17 + b];
        float nv = irow[i] + __fdiv_rn(corr, 180.0f);
        irow[i] = nv;
        Dsh[x * 17 + b] = nv;                 // stage for prefix (own slot)
        mx = fmaxf(mx, nv);
    }
    if (last) {
        #pragma unroll
        for (int off = 16; off; off >>= 1)
            mx = fmaxf(mx, __shfl_xor_sync(0xffffffffu, mx, off));
        if (lane == 0) blockmax[w] = mx;
    }
    __syncthreads();
    // Phase E: inclusive prefix of new row -> g_P; same fast scan
    {
        float s[8];
        int base = lane * 8;
        #pragma unroll
        for (int k = 0; k < 8; k++) s[k] = Dsh[(base + k) * 17 + w];
        #pragma unroll
        for (int k = 1; k < 8; k++) s[k] += s[k - 1];
        float tot = s[7], inc = tot;
        #pragma unroll
        for (int off = 1; off < 32; off <<= 1) {
            float nn = __shfl_up_sync(0xffffffffu, inc, off);
            if (lane >= off) inc += nn;
        }
        float excl2 = inc - tot;
        #pragma unroll
        for (int k = 0; k < 8; k++) Dsh[(base + k) * 17 + w] = s[k] + excl2;
    }
    __syncthreads();
    #pragma unroll
    for (int k = 0; k < 8; k++) {
        int i = t + k * 512;
        int x = i >> 4, b = i & 15;
        g_P[((size_t)y * 257 + x + 1) * NB + b] = Dsh[x * 17 + b];
    }
    if (last && t == 0) {
        float m = blockmax[0];
        #pragma unroll
        for (int k = 1; k < 16; k++) m = fmaxf(m, blockmax[k]);
        unsigned u = __float_as_uint(m);
        u = (u & 0x80000000u) ? ~u : (u | 0x80000000u);
        atomicMax(&g_maxbits, u);
    }
}

// fused FP: blocks [0, 5760) interior runs; blocks [5760, 6120) terminal bins
__global__ __launch_bounds__(256) void k_fpx() {
    __shared__ ushort4 sm2[256];
    __shared__ float red[16 * 17];
    int bx = blockIdx.x;
    int t = threadIdx.x;
    if (bx < NRC / 8) {
        // interior FP: warp per (a,d), zero atomics, MLP 8
        int wi = bx * 8 + (t >> 5);
        int d = wi & 255;
        if (d == 0 || d == 255) return;                  // terminal handled below
        int lane = t & 31, half = lane >> 4, b = lane & 15;
        int n = g_cnt[wi];
        const unsigned* runs = g_runs + (size_t)wi * CAP;
        float acc = 0.0f, acc2 = 0.0f, acc3 = 0.0f, acc4 = 0.0f;
        int r = half;
        for (; r + 6 < n; r += 8) {
            unsigned r1 = runs[r], r2 = runs[r + 2], r3 = runs[r + 4], r4 = runs[r + 6];
            const float* P1 = g_P + (size_t)(r1 & 255) * 257 * NB;
            const float* P2 = g_P + (size_t)(r2 & 255) * 257 * NB;
            const float* P3 = g_P + (size_t)(r3 & 255) * 257 * NB;
            const float* P4 = g_P + (size_t)(r4 & 255) * 257 * NB;
            acc  += P1[((r1 >> 17) & 511) * NB + b] - P1[((r1 >> 8) & 511) * NB + b];
            acc2 += P2[((r2 >> 17) & 511) * NB + b] - P2[((r2 >> 8) & 511) * NB + b];
            acc3 += P3[((r3 >> 17) & 511) * NB + b] - P3[((r3 >> 8) & 511) * NB + b];
            acc4 += P4[((r4 >> 17) & 511) * NB + b] - P4[((r4 >> 8) & 511) * NB + b];
        }
        for (; r < n; r += 2) {
            unsigned rec = runs[r];
            const float* Pr = g_P + (size_t)(rec & 255) * 257 * NB;
            acc += Pr[((rec >> 17) & 511) * NB + b] - Pr[((rec >> 8) & 511) * NB + b];
        }
        acc = (acc + acc2) + (acc3 + acc4);
        acc += __shfl_xor_sync(0xffffffffu, acc, 16);
        if (half == 0)
            g_R[(size_t)wi * NB + b] = g_SN[(size_t)wi * NB + b] - acc;
        return;
    }
    // terminal bins d in {0,255}: block per (a,side)
    int bx2 = bx - NRC / 8;
    int a = bx2 >> 1;
    int d = (bx2 & 1) ? 255 : 0;
    sm2[t] = g_meta[a * NH + t];
    __syncthreads();
    int b = t & 15, yg = t >> 4;
    float acc = 0.0f;
    #pragma unroll 4
    for (int i = 0; i < 16; i++) {
        int y = yg * 16 + i;
        ushort4 m = sm2[y];
        const float* Pr = g_P + (size_t)y * 257 * NB;
        if ((int)m.z == d)        acc += Pr[(int)m.x * NB + b];
        else if ((int)m.w == d)   acc += Pr[256 * NB + b] - Pr[(int)m.y * NB + b];
    }
    red[yg * 17 + b] = acc;
    __syncthreads();
    if (t < 16) {
        float s = 0.0f;
        #pragma unroll
        for (int g = 0; g < 16; g++) s += red[g * 17 + t];
        int wi = a * ND + d;
        g_R[(size_t)wi * NB + t] = g_SN[(size_t)wi * NB + t] - s;
    }
}

// output: clip(image, 0, gmax), coalesced transpose [p][b] -> [b][p]
__global__ __launch_bounds__(256) void k_out(float* __restrict__ out) {
    __shared__ float sh[256 * 17];
    int t = threadIdx.x;
    int p0 = blockIdx.x * 256;
    const float* src = g_img + (size_t)p0 * NB;
    for (int i = t; i < 256 * NB; i += 256) {
        int p = i >> 4, b = i & 15;
        sh[p * 17 + b] = src[i];
    }
    __syncthreads();
    unsigned u = g_maxbits;
    float gm = (u & 0x80000000u) ? __uint_as_float(u ^ 0x80000000u)
                                 : __uint_as_float(~u);
    #pragma unroll
    for (int b = 0; b < NB; b++) {
        float v = sh[t * 17 + b];
        out[(size_t)b * NP + p0 + t] = fminf(fmaxf(v, 0.0f), gm);
    }
}

extern "C" void kernel_launch(void* const* d_in, const int* in_sizes, int n_in,
                              void* d_out, int out_size) {
    const float* sino = (const float*)d_in[0];
    float* out = (float*)d_out;

    static int smem_set = 0;
    if (!smem_set) {
        cudaFuncSetAttribute(k_bp, cudaFuncAttributeMaxDynamicSharedMemorySize,
                             SMEM_BYTES);
        smem_set = 1;
    }

    k_pre<<<512, 256>>>(sino);
    k_binsfill<<<dim3(NA, 8), 256>>>();
    k_bp<<<NH, 512, SMEM_BYTES>>>(0);
    for (int it = 1; it < NT; it++) {
        k_fpx<<<NRC / 8 + NA * 2, 256>>>();  // it==1 -> launch #4 -> ncu target
        k_bp<<<NH, 512, SMEM_BYTES>>>(it == NT - 1 ? 1 : 0);
    }
    k_out<<<256, 256>>>(out);
}